// round 2
// baseline (speedup 1.0000x reference)
#include <cuda_runtime.h>
#include <cstdint>

#define N_ROWS 32768
#define DIM    512
#define K_CODES 8192

#define BM 128
#define BN 128
#define BK 8
#define TM 8
#define TN 8
#define PAD 4   // smem row padding (floats) -> 132-float rows, kills store conflicts

// Scratch (no allocations allowed): per-row best (key<<32 | col), codebook norms.
__device__ unsigned long long g_best[N_ROWS];
__device__ float g_cnorm[K_CODES];

// ---------------------------------------------------------------------------
// Kernel 1: codebook row norms + reset g_best. One warp per codebook row.
// ---------------------------------------------------------------------------
__global__ void prep_kernel(const float* __restrict__ codebook) {
    int tid  = blockIdx.x * blockDim.x + threadIdx.x;
    int warp = tid >> 5;
    int lane = threadIdx.x & 31;
    if (warp < K_CODES) {
        const float4* row = (const float4*)(codebook + (size_t)warp * DIM);
        float s = 0.f;
        #pragma unroll
        for (int i = lane; i < DIM / 4; i += 32) {
            float4 v = row[i];
            s += v.x * v.x + v.y * v.y + v.z * v.z + v.w * v.w;
        }
        #pragma unroll
        for (int o = 16; o > 0; o >>= 1) s += __shfl_down_sync(0xffffffffu, s, o);
        if (lane == 0) g_cnorm[warp] = s;
    }
    if (tid < N_ROWS) g_best[tid] = 0xFFFFFFFFFFFFFFFFull;
}

// ---------------------------------------------------------------------------
// Kernel 2: fused fp32 GEMM (X @ C^T) + per-row argmin of (||c||^2 - 2 x.c).
// Classic 128x128x8 tile, 8x8 register micro-tile, 256 threads.
// ---------------------------------------------------------------------------
__device__ __forceinline__ unsigned float_to_ordered(float f) {
    unsigned u = __float_as_uint(f);
    // negative -> flip all bits; positive -> flip sign bit. Monotone total order.
    return u ^ (unsigned)(((int)u >> 31) | 0x80000000);
}

__global__ __launch_bounds__(256, 2)
void gemm_argmin_kernel(const float* __restrict__ X, const float* __restrict__ C) {
    __shared__ float As[BK][BM + PAD];
    __shared__ float Bs[BK][BN + PAD];

    const int tid  = threadIdx.x;
    const int row0 = blockIdx.y * BM;
    const int col0 = blockIdx.x * BN;

    // global->smem load mapping: 256 threads, each one float4; 2 segs per row
    const int la_row = tid >> 1;         // 0..127
    const int la_seg = (tid & 1) * 4;    // 0 or 4
    const float* Aptr = X + (size_t)(row0 + la_row) * DIM + la_seg;
    const float* Bptr = C + (size_t)(col0 + la_row) * DIM + la_seg;

    // compute mapping: 16x16 thread grid of 8x8 micro-tiles
    const int tm = (tid >> 4) * TM;      // row offset in tile
    const int tn = (tid & 15) * TN;      // col offset in tile

    float acc[TM][TN];
    #pragma unroll
    for (int i = 0; i < TM; i++)
        #pragma unroll
        for (int j = 0; j < TN; j++) acc[i][j] = 0.f;

    for (int k = 0; k < DIM; k += BK) {
        float4 a = *(const float4*)(Aptr + k);
        float4 b = *(const float4*)(Bptr + k);
        if (k != 0) __syncthreads();   // protect smem reuse from previous iter
        As[la_seg + 0][la_row] = a.x;
        As[la_seg + 1][la_row] = a.y;
        As[la_seg + 2][la_row] = a.z;
        As[la_seg + 3][la_row] = a.w;
        Bs[la_seg + 0][la_row] = b.x;
        Bs[la_seg + 1][la_row] = b.y;
        Bs[la_seg + 2][la_row] = b.z;
        Bs[la_seg + 3][la_row] = b.w;
        __syncthreads();

        #pragma unroll
        for (int kk = 0; kk < BK; kk++) {
            float4 a0 = *(const float4*)&As[kk][tm];
            float4 a1 = *(const float4*)&As[kk][tm + 4];
            float4 b0 = *(const float4*)&Bs[kk][tn];
            float4 b1 = *(const float4*)&Bs[kk][tn + 4];
            float ar[TM] = {a0.x, a0.y, a0.z, a0.w, a1.x, a1.y, a1.z, a1.w};
            float br[TN] = {b0.x, b0.y, b0.z, b0.w, b1.x, b1.y, b1.z, b1.w};
            #pragma unroll
            for (int i = 0; i < TM; i++)
                #pragma unroll
                for (int j = 0; j < TN; j++)
                    acc[i][j] = fmaf(ar[i], br[j], acc[i][j]);
        }
    }

    // Epilogue: dist = ||c||^2 - 2*dot  (||x||^2 dropped: constant per row)
    float cn[TN];
    #pragma unroll
    for (int j = 0; j < TN; j++) cn[j] = g_cnorm[col0 + tn + j];

    #pragma unroll
    for (int i = 0; i < TM; i++) {
        float best_d = cn[0] - 2.f * acc[i][0];
        int   best_j = 0;
        #pragma unroll
        for (int j = 1; j < TN; j++) {
            float d = cn[j] - 2.f * acc[i][j];
            if (d < best_d) { best_d = d; best_j = j; }   // ascending j: ties -> lowest col
        }
        unsigned long long p =
            ((unsigned long long)float_to_ordered(best_d) << 32) |
            (unsigned)(col0 + tn + best_j);
        // reduce across the 16 threads covering this row (contiguous 16-lane group)
        #pragma unroll
        for (int off = 8; off > 0; off >>= 1) {
            unsigned long long q = __shfl_down_sync(0xffffffffu, p, off, 16);
            if (q < p) p = q;
        }
        if ((tid & 15) == 0)
            atomicMin(&g_best[row0 + tm + i], p);
    }
}

// ---------------------------------------------------------------------------
// Kernel 3: gather codebook[argmin] into both output halves.
// ---------------------------------------------------------------------------
__global__ void gather_kernel(const float* __restrict__ C, float* __restrict__ out) {
    int n = blockIdx.x;
    unsigned idx = (unsigned)(g_best[n] & 0xFFFFFFFFull);
    const float4* src = (const float4*)(C + (size_t)idx * DIM);
    float4* d0 = (float4*)(out + (size_t)n * DIM);
    float4* d1 = (float4*)(out + ((size_t)N_ROWS + n) * DIM);
    int i = threadIdx.x;            // 128 threads, DIM/4 = 128 float4
    float4 v = src[i];
    d0[i] = v;
    d1[i] = v;
}

// ---------------------------------------------------------------------------
extern "C" void kernel_launch(void* const* d_in, const int* in_sizes, int n_in,
                              void* d_out, int out_size) {
    const float* x  = (const float*)d_in[0];   // [N, D] fp32
    const float* cb = (const float*)d_in[1];   // [K, D] fp32
    float* out = (float*)d_out;                // [2, N, D] fp32

    (void)in_sizes; (void)n_in; (void)out_size;

    // 1) norms + best reset: K_CODES warps = 262144 threads
    prep_kernel<<<(K_CODES * 32) / 256, 256>>>(cb);

    // 2) fused GEMM+argmin: grid (K/BN, N/BM) = (64, 256)
    dim3 grid(K_CODES / BN, N_ROWS / BM);
    gemm_argmin_kernel<<<grid, 256>>>(x, cb);

    // 3) gather into both halves
    gather_kernel<<<N_ROWS, 128>>>(cb, out);
}

// round 8
// speedup vs baseline: 2.8207x; 2.8207x over previous
#include <cuda_runtime.h>
#include <cuda_fp16.h>
#include <cstdint>

#define N_ROWS 32768
#define DIM    512
#define K_CODES 8192

#define BM 128
#define BN 128
#define KC 64                    // k per chunk: 64 fp16 = 128B rows
#define NCHUNK (DIM / KC)        // 8 per phase
#define NPHASE 3                 // hh, mh, hm (all scale-1 products)
#define NVC (NPHASE * NCHUNK)    // 24 virtual chunks
#define TILE_BYTES 16384         // 128 rows x 128B
#define STAGE_BYTES (2 * TILE_BYTES)   // A + B
#define SMEM_TOTAL (2 * STAGE_BYTES)   // double buffered = 64KB

// ---- scratch ----
__device__ unsigned long long g_best[N_ROWS];
__device__ float g_cnorm[K_CODES];
__device__ __half g_Xh [(size_t)N_ROWS * DIM];
__device__ __half g_Xm [(size_t)N_ROWS * DIM];
__device__ __half g_Ch [(size_t)K_CODES * DIM];
__device__ __half g_Cm64[(size_t)K_CODES * DIM];  // (c - Ch) * 64

// ---- helpers ----
__device__ __forceinline__ uint32_t smem_u32(const void* p) {
    uint32_t a;
    asm("{ .reg .u64 t; cvta.to.shared.u64 t, %1; cvt.u32.u64 %0, t; }" : "=r"(a) : "l"(p));
    return a;
}
#define CP_ASYNC16(dst, src) \
    asm volatile("cp.async.cg.shared.global [%0], [%1], 16;" :: "r"(dst), "l"(src) : "memory")
#define CP_COMMIT() asm volatile("cp.async.commit_group;" ::: "memory")

__device__ __forceinline__ void ldmatrix_x4(uint32_t* r, uint32_t addr) {
    asm volatile("ldmatrix.sync.aligned.m8n8.x4.shared.b16 {%0,%1,%2,%3}, [%4];"
                 : "=r"(r[0]), "=r"(r[1]), "=r"(r[2]), "=r"(r[3]) : "r"(addr));
}
__device__ __forceinline__ void mma_16816(float* d, const uint32_t* a, uint32_t b0, uint32_t b1) {
    asm volatile(
        "mma.sync.aligned.m16n8k16.row.col.f32.f16.f16.f32 "
        "{%0,%1,%2,%3}, {%4,%5,%6,%7}, {%8,%9}, {%0,%1,%2,%3};"
        : "+f"(d[0]), "+f"(d[1]), "+f"(d[2]), "+f"(d[3])
        : "r"(a[0]), "r"(a[1]), "r"(a[2]), "r"(a[3]), "r"(b0), "r"(b1));
}
__device__ __forceinline__ uint32_t sw128(uint32_t off) {
    return off ^ ((off >> 3) & 0x70);
}
__device__ __forceinline__ unsigned float_to_ordered(float f) {
    unsigned u = __float_as_uint(f);
    return u ^ (unsigned)(((int)u >> 31) | 0x80000000);
}

// ========================= prep kernels ====================================
// X split: Xh = rn(x); Xm = rn(x - Xh).
__global__ void split_x_kernel(const float* __restrict__ src, int n4) {
    int i = blockIdx.x * blockDim.x + threadIdx.x;
    if (i >= n4) return;
    float4 v = ((const float4*)src)[i];
    float vv[4] = {v.x, v.y, v.z, v.w};
    __half h[4], m[4];
    #pragma unroll
    for (int k = 0; k < 4; k++) {
        float f = vv[k];
        h[k] = __float2half_rn(f);
        m[k] = __float2half_rn(f - __half2float(h[k]));
    }
    ((__half2*)g_Xh)[i * 2 + 0] = __half2(h[0], h[1]);
    ((__half2*)g_Xh)[i * 2 + 1] = __half2(h[2], h[3]);
    ((__half2*)g_Xm)[i * 2 + 0] = __half2(m[0], m[1]);
    ((__half2*)g_Xm)[i * 2 + 1] = __half2(m[2], m[3]);
}
// C split: Ch = rn(c); Cm64 = rn((c - Ch) * 64)  (normal range in fp16).
__global__ void split_c_kernel(const float* __restrict__ src, int n4) {
    int i = blockIdx.x * blockDim.x + threadIdx.x;
    if (i >= n4) return;
    float4 v = ((const float4*)src)[i];
    float vv[4] = {v.x, v.y, v.z, v.w};
    __half h[4], m[4];
    #pragma unroll
    for (int k = 0; k < 4; k++) {
        float f = vv[k];
        h[k] = __float2half_rn(f);
        m[k] = __float2half_rn((f - __half2float(h[k])) * 64.0f);
    }
    ((__half2*)g_Ch  )[i * 2 + 0] = __half2(h[0], h[1]);
    ((__half2*)g_Ch  )[i * 2 + 1] = __half2(h[2], h[3]);
    ((__half2*)g_Cm64)[i * 2 + 0] = __half2(m[0], m[1]);
    ((__half2*)g_Cm64)[i * 2 + 1] = __half2(m[2], m[3]);
}

__global__ void prep_kernel(const float* __restrict__ codebook) {
    int tid  = blockIdx.x * blockDim.x + threadIdx.x;
    int warp = tid >> 5;
    int lane = threadIdx.x & 31;
    if (warp < K_CODES) {
        const float4* row = (const float4*)(codebook + (size_t)warp * DIM);
        float s = 0.f;
        #pragma unroll
        for (int i = lane; i < DIM / 4; i += 32) {
            float4 v = row[i];
            s += v.x * v.x + v.y * v.y + v.z * v.z + v.w * v.w;
        }
        #pragma unroll
        for (int o = 16; o > 0; o >>= 1) s += __shfl_down_sync(0xffffffffu, s, o);
        if (lane == 0) g_cnorm[warp] = s;
    }
    if (tid < N_ROWS) g_best[tid] = 0xFFFFFFFFFFFFFFFFull;
}

// ================== fused mma.sync GEMM + argmin ===========================
// phase 0: Xh*Ch,  phase 1: Xm*Ch,  phase 2: (Xh*2^-6 in regs)*Cm64
__device__ __forceinline__ void issue_loads(int vc, int stage, uint32_t smbase,
                                            int row0, int col0, int tid) {
    const int phase = vc >> 3;
    const int kof   = (vc & 7) * KC;
    const __half* asrc = (phase == 1) ? g_Xm : g_Xh;
    const __half* bsrc = (phase == 2) ? g_Cm64 : g_Ch;
    const uint32_t sa = smbase + stage * STAGE_BYTES;
    const uint32_t sb = sa + TILE_BYTES;
    #pragma unroll
    for (int j = 0; j < 4; j++) {
        int o = tid + j * 256, r = o >> 3, seg = o & 7;
        uint32_t sw = sw128((uint32_t)(r * 128 + seg * 16));
        CP_ASYNC16(sa + sw, asrc + (size_t)(row0 + r) * DIM + kof + seg * 8);
        CP_ASYNC16(sb + sw, bsrc + (size_t)(col0 + r) * DIM + kof + seg * 8);
    }
}

__global__ void __launch_bounds__(256, 2)
gemm_argmin_mma(void) {
    extern __shared__ char smem[];
    const uint32_t smbase = smem_u32(smem);
    const int tid  = threadIdx.x;
    const int wid  = tid >> 5;
    const int lane = tid & 31;
    const int warp_m = wid >> 2;      // 0..1  (64 rows each)
    const int warp_n = wid & 3;       // 0..3  (32 cols each)
    const int row0 = blockIdx.y * BM;
    const int col0 = blockIdx.x * BN;

    float acc[4][4][4];               // [mi][ni][reg]
    #pragma unroll
    for (int a = 0; a < 4; a++)
        #pragma unroll
        for (int b = 0; b < 4; b++)
            #pragma unroll
            for (int c = 0; c < 4; c++) acc[a][b][c] = 0.f;

    const int a_row = warp_m * 64 + (lane & 7) + 8 * ((lane >> 3) & 1); // + mi*16
    const int a_cb0 = (lane >> 4) * 16;                                  // + ks*32
    const int b_row = warp_n * 32 + (lane & 7) + 8 * (lane >> 4);        // + nj*16
    const int b_cb0 = ((lane >> 3) & 1) * 16;                            // + ks*32

    issue_loads(0, 0, smbase, row0, col0, tid);
    CP_COMMIT();

    #pragma unroll 1
    for (int vc = 0; vc < NVC; vc++) {
        const int s = vc & 1;
        if (vc + 1 < NVC) {
            issue_loads(vc + 1, s ^ 1, smbase, row0, col0, tid);
            CP_COMMIT();
            asm volatile("cp.async.wait_group 1;" ::: "memory");
        } else {
            asm volatile("cp.async.wait_group 0;" ::: "memory");
        }
        __syncthreads();

        const bool scaleA = (vc >= 2 * NCHUNK);   // phase 2
        const uint32_t sa = smbase + s * STAGE_BYTES;
        const uint32_t sb = sa + TILE_BYTES;
        #pragma unroll
        for (int ks = 0; ks < KC / 16; ks++) {
            uint32_t afr[4][4], bfr[2][4];
            #pragma unroll
            for (int mi = 0; mi < 4; mi++) {
                uint32_t off = (uint32_t)((a_row + mi * 16) * 128 + ks * 32 + a_cb0);
                ldmatrix_x4(afr[mi], sa + sw128(off));
            }
            if (scaleA) {
                const __half2 sc = __float2half2_rn(0.015625f);   // 2^-6 exact
                #pragma unroll
                for (int mi = 0; mi < 4; mi++)
                    #pragma unroll
                    for (int r = 0; r < 4; r++) {
                        __half2 v = *reinterpret_cast<__half2*>(&afr[mi][r]);
                        v = __hmul2(v, sc);
                        afr[mi][r] = *reinterpret_cast<uint32_t*>(&v);
                    }
            }
            #pragma unroll
            for (int nj = 0; nj < 2; nj++) {
                uint32_t off = (uint32_t)((b_row + nj * 16) * 128 + ks * 32 + b_cb0);
                ldmatrix_x4(bfr[nj], sb + sw128(off));
            }
            #pragma unroll
            for (int mi = 0; mi < 4; mi++)
                #pragma unroll
                for (int ni = 0; ni < 4; ni++) {
                    const uint32_t* bf = bfr[ni >> 1];
                    uint32_t b0 = (ni & 1) ? bf[2] : bf[0];
                    uint32_t b1 = (ni & 1) ? bf[3] : bf[1];
                    mma_16816(acc[mi][ni], afr[mi], b0, b1);
                }
        }
        __syncthreads();
    }

    // ---- argmin epilogue ----
    float cn[4][2];
    #pragma unroll
    for (int ni = 0; ni < 4; ni++) {
        int col = col0 + warp_n * 32 + ni * 8 + (lane & 3) * 2;
        cn[ni][0] = __ldg(&g_cnorm[col]);
        cn[ni][1] = __ldg(&g_cnorm[col + 1]);
    }
    #pragma unroll
    for (int mi = 0; mi < 4; mi++) {
        #pragma unroll
        for (int rp = 0; rp < 2; rp++) {
            float best_d = 3.4e38f;
            int   best_c = 0;
            #pragma unroll
            for (int ni = 0; ni < 4; ni++) {
                #pragma unroll
                for (int c = 0; c < 2; c++) {
                    int col = col0 + warp_n * 32 + ni * 8 + (lane & 3) * 2 + c;
                    float d = cn[ni][c] - 2.0f * acc[mi][ni][rp * 2 + c];
                    if (d < best_d) { best_d = d; best_c = col; }
                }
            }
            unsigned long long p =
                ((unsigned long long)float_to_ordered(best_d) << 32) | (unsigned)best_c;
            #pragma unroll
            for (int m = 1; m < 4; m <<= 1) {
                unsigned long long q = __shfl_xor_sync(0xffffffffu, p, m);
                if (q < p) p = q;
            }
            if ((lane & 3) == 0) {
                int row = row0 + warp_m * 64 + mi * 16 + (lane >> 2) + 8 * rp;
                atomicMin(&g_best[row], p);
            }
        }
    }
}

// ============================ gather =======================================
// out0 = q;  out1 = x + (q - x) with fp32 rounding, mimicking the reference.
__global__ void gather_kernel(const float* __restrict__ C, const float* __restrict__ X,
                              float* __restrict__ out) {
    int n = blockIdx.x;
    unsigned idx = (unsigned)(g_best[n] & 0xFFFFFFFFull);
    const float4* src = (const float4*)(C + (size_t)idx * DIM);
    const float4* xs  = (const float4*)(X + (size_t)n * DIM);
    float4* d0 = (float4*)(out + (size_t)n * DIM);
    float4* d1 = (float4*)(out + ((size_t)N_ROWS + n) * DIM);
    int i = threadIdx.x;
    float4 q = src[i];
    float4 x = xs[i];
    d0[i] = q;
    float4 st;
    st.x = x.x + (q.x - x.x);
    st.y = x.y + (q.y - x.y);
    st.z = x.z + (q.z - x.z);
    st.w = x.w + (q.w - x.w);
    d1[i] = st;
}

// ===========================================================================
extern "C" void kernel_launch(void* const* d_in, const int* in_sizes, int n_in,
                              void* d_out, int out_size) {
    const float* x  = (const float*)d_in[0];
    const float* cb = (const float*)d_in[1];
    float* out = (float*)d_out;
    (void)in_sizes; (void)n_in; (void)out_size;

    cudaFuncSetAttribute(gemm_argmin_mma,
                         cudaFuncAttributeMaxDynamicSharedMemorySize, SMEM_TOTAL);

    split_x_kernel<<<(N_ROWS * DIM / 4 + 255) / 256, 256>>>(x, N_ROWS * DIM / 4);
    split_c_kernel<<<(K_CODES * DIM / 4 + 255) / 256, 256>>>(cb, K_CODES * DIM / 4);
    prep_kernel<<<(K_CODES * 32) / 256, 256>>>(cb);

    dim3 grid(K_CODES / BN, N_ROWS / BM);   // (64, 256)
    gemm_argmin_mma<<<grid, 256, SMEM_TOTAL>>>();

    gather_kernel<<<N_ROWS, 128>>>(cb, x, out);
}

// round 11
// speedup vs baseline: 5.7242x; 2.0294x over previous
#include <cuda_runtime.h>
#include <cuda_fp16.h>
#include <cstdint>
#include <cfloat>

#define N_ROWS 32768
#define DIM    512
#define K_CODES 8192

#define BM 128
#define BN 128
#define KC 64                    // 64 fp16 = 128B rows
#define NVC (DIM / KC)           // 8 chunks (hh only)
#define TILE_BYTES 16384         // 128 rows x 128B
#define STAGE_BYTES (2 * TILE_BYTES)   // A + B = 32KB
#define NSTAGE 3
#define SMEM_TOTAL (NSTAGE * STAGE_BYTES)   // 96KB
#define CAP 256                  // candidate slots per row

// statistical margin: err std sigma_d ~= 1.21e-5 * ||x||_2 ; margin ~= 20 sigma
#define MARGIN_A 2.5e-4f
#define MARGIN_B 3.0e-4f

// ---- scratch ----
__device__ unsigned long long g_best[N_ROWS];      // approx (orderedkey<<32|col)
__device__ unsigned int  g_idx[N_ROWS];            // final argmin
__device__ float         g_margin[N_ROWS];
__device__ unsigned int  g_candcnt[N_ROWS];
__device__ unsigned int  g_cand[(size_t)N_ROWS * CAP];   // columns only (32MB)
__device__ float g_cnorm_arr[K_CODES];
__device__ __half g_Xh[(size_t)N_ROWS * DIM];
__device__ __half g_Ch[(size_t)K_CODES * DIM];

// ---- helpers ----
__device__ __forceinline__ uint32_t smem_u32(const void* p) {
    uint32_t a;
    asm("{ .reg .u64 t; cvta.to.shared.u64 t, %1; cvt.u32.u64 %0, t; }" : "=r"(a) : "l"(p));
    return a;
}
#define CP_ASYNC16(dst, src) \
    asm volatile("cp.async.cg.shared.global [%0], [%1], 16;" :: "r"(dst), "l"(src) : "memory")
#define CP_COMMIT() asm volatile("cp.async.commit_group;" ::: "memory")

__device__ __forceinline__ void ldmatrix_x4(uint32_t* r, uint32_t addr) {
    asm volatile("ldmatrix.sync.aligned.m8n8.x4.shared.b16 {%0,%1,%2,%3}, [%4];"
                 : "=r"(r[0]), "=r"(r[1]), "=r"(r[2]), "=r"(r[3]) : "r"(addr));
}
__device__ __forceinline__ void mma_16816(float* d, const uint32_t* a, uint32_t b0, uint32_t b1) {
    asm volatile(
        "mma.sync.aligned.m16n8k16.row.col.f32.f16.f16.f32 "
        "{%0,%1,%2,%3}, {%4,%5,%6,%7}, {%8,%9}, {%0,%1,%2,%3};"
        : "+f"(d[0]), "+f"(d[1]), "+f"(d[2]), "+f"(d[3])
        : "r"(a[0]), "r"(a[1]), "r"(a[2]), "r"(a[3]), "r"(b0), "r"(b1));
}
__device__ __forceinline__ uint32_t sw128(uint32_t off) { return off ^ ((off >> 3) & 0x70); }
__device__ __forceinline__ unsigned float_to_ordered(float f) {
    unsigned u = __float_as_uint(f);
    return u ^ (unsigned)(((int)u >> 31) | 0x80000000);
}
__device__ __forceinline__ float ordered_to_float(unsigned u) {
    unsigned v = (u & 0x80000000u) ? (u ^ 0x80000000u) : ~u;
    return __uint_as_float(v);
}

// ========================= prep kernels ====================================
__global__ void split_x_kernel(const float* __restrict__ src, int n4) {
    int i = blockIdx.x * blockDim.x + threadIdx.x;
    if (i >= n4) return;
    float4 v = ((const float4*)src)[i];
    ((__half2*)g_Xh)[i * 2 + 0] = __half2(__float2half_rn(v.x), __float2half_rn(v.y));
    ((__half2*)g_Xh)[i * 2 + 1] = __half2(__float2half_rn(v.z), __float2half_rn(v.w));
}
__global__ void split_c_kernel(const float* __restrict__ src, int n4) {
    int i = blockIdx.x * blockDim.x + threadIdx.x;
    if (i >= n4) return;
    float4 v = ((const float4*)src)[i];
    ((__half2*)g_Ch)[i * 2 + 0] = __half2(__float2half_rn(v.x), __float2half_rn(v.y));
    ((__half2*)g_Ch)[i * 2 + 1] = __half2(__float2half_rn(v.z), __float2half_rn(v.w));
}
// per-row margin (from ||x||_2) + state reset. one warp per row.
__global__ void prep_x_kernel(const float* __restrict__ X) {
    int warp = (blockIdx.x * blockDim.x + threadIdx.x) >> 5;
    int lane = threadIdx.x & 31;
    if (warp >= N_ROWS) return;
    const float4* row = (const float4*)(X + (size_t)warp * DIM);
    float s = 0.f;
    #pragma unroll
    for (int i = lane; i < DIM / 4; i += 32) {
        float4 v = row[i];
        s += v.x * v.x + v.y * v.y + v.z * v.z + v.w * v.w;
    }
    #pragma unroll
    for (int o = 16; o > 0; o >>= 1) s += __shfl_down_sync(0xffffffffu, s, o);
    if (lane == 0) {
        g_margin[warp]  = MARGIN_A * sqrtf(s) + MARGIN_B;
        g_best[warp]    = 0xFFFFFFFFFFFFFFFFull;
        g_candcnt[warp] = 0u;
    }
}
__global__ void prep_c_kernel(const float* __restrict__ codebook) {
    int warp = (blockIdx.x * blockDim.x + threadIdx.x) >> 5;
    int lane = threadIdx.x & 31;
    if (warp >= K_CODES) return;
    const float4* row = (const float4*)(codebook + (size_t)warp * DIM);
    float s = 0.f;
    #pragma unroll
    for (int i = lane; i < DIM / 4; i += 32) {
        float4 v = row[i];
        s += v.x * v.x + v.y * v.y + v.z * v.z + v.w * v.w;
    }
    #pragma unroll
    for (int o = 16; o > 0; o >>= 1) s += __shfl_down_sync(0xffffffffu, s, o);
    if (lane == 0) g_cnorm_arr[warp] = s;
}

// ================== pass 1: hh GEMM + argmin + candidate dump ==============
__device__ __forceinline__ void issue_loads(int vc, int stage, uint32_t smbase,
                                            int row0, int col0, int tid) {
    const int kof = vc * KC;
    const uint32_t sa = smbase + stage * STAGE_BYTES;
    const uint32_t sb = sa + TILE_BYTES;
    #pragma unroll
    for (int j = 0; j < 4; j++) {
        int o = tid + j * 256, r = o >> 3, seg = o & 7;
        uint32_t sw = sw128((uint32_t)(r * 128 + seg * 16));
        CP_ASYNC16(sa + sw, g_Xh + (size_t)(row0 + r) * DIM + kof + seg * 8);
        CP_ASYNC16(sb + sw, g_Ch + (size_t)(col0 + r) * DIM + kof + seg * 8);
    }
}

__global__ void __launch_bounds__(256, 2)
gemm_argmin_mma(void) {
    extern __shared__ char smem[];
    const uint32_t smbase = smem_u32(smem);
    const int tid  = threadIdx.x;
    const int wid  = tid >> 5;
    const int lane = tid & 31;
    const int warp_m = wid >> 2;
    const int warp_n = wid & 3;
    const int row0 = blockIdx.y * BM;
    const int col0 = blockIdx.x * BN;

    float acc[4][4][4];
    #pragma unroll
    for (int a = 0; a < 4; a++)
        #pragma unroll
        for (int b = 0; b < 4; b++)
            #pragma unroll
            for (int c = 0; c < 4; c++) acc[a][b][c] = 0.f;

    const int a_row = warp_m * 64 + (lane & 7) + 8 * ((lane >> 3) & 1);
    const int a_cb0 = (lane >> 4) * 16;
    const int b_row = warp_n * 32 + (lane & 7) + 8 * (lane >> 4);
    const int b_cb0 = ((lane >> 3) & 1) * 16;

    issue_loads(0, 0, smbase, row0, col0, tid);
    CP_COMMIT();
    issue_loads(1, 1, smbase, row0, col0, tid);
    CP_COMMIT();

    #pragma unroll 1
    for (int vc = 0; vc < NVC; vc++) {
        if (vc < NVC - 1) asm volatile("cp.async.wait_group 1;" ::: "memory");
        else              asm volatile("cp.async.wait_group 0;" ::: "memory");
        __syncthreads();
        if (vc + 2 < NVC) {
            issue_loads(vc + 2, (vc + 2) % NSTAGE, smbase, row0, col0, tid);
            CP_COMMIT();
        }
        const uint32_t sa = smbase + (vc % NSTAGE) * STAGE_BYTES;
        const uint32_t sb = sa + TILE_BYTES;
        #pragma unroll
        for (int ks = 0; ks < KC / 16; ks++) {
            uint32_t afr[4][4], bfr[2][4];
            #pragma unroll
            for (int mi = 0; mi < 4; mi++) {
                uint32_t off = (uint32_t)((a_row + mi * 16) * 128 + ks * 32 + a_cb0);
                ldmatrix_x4(afr[mi], sa + sw128(off));
            }
            #pragma unroll
            for (int nj = 0; nj < 2; nj++) {
                uint32_t off = (uint32_t)((b_row + nj * 16) * 128 + ks * 32 + b_cb0);
                ldmatrix_x4(bfr[nj], sb + sw128(off));
            }
            #pragma unroll
            for (int mi = 0; mi < 4; mi++)
                #pragma unroll
                for (int ni = 0; ni < 4; ni++) {
                    const uint32_t* bf = bfr[ni >> 1];
                    uint32_t b0 = (ni & 1) ? bf[2] : bf[0];
                    uint32_t b1 = (ni & 1) ? bf[3] : bf[1];
                    mma_16816(acc[mi][ni], afr[mi], b0, b1);
                }
        }
        // stage (vc+2)%3 written next iter was last read at vc-1; the barrier
        // at the top of iteration vc+1 orders the reuse.
    }

    // ---- epilogue: approx argmin + live-threshold candidate dump ----
    float cn[4][2];
    #pragma unroll
    for (int ni = 0; ni < 4; ni++) {
        int col = col0 + warp_n * 32 + ni * 8 + (lane & 3) * 2;
        cn[ni][0] = __ldg(&g_cnorm_arr[col]);
        cn[ni][1] = __ldg(&g_cnorm_arr[col + 1]);
    }
    #pragma unroll
    for (int mi = 0; mi < 4; mi++) {
        #pragma unroll
        for (int rp = 0; rp < 2; rp++) {
            const int row = row0 + warp_m * 64 + mi * 16 + (lane >> 2) + 8 * rp;
            float best_d = FLT_MAX;
            int   best_c = 0;
            #pragma unroll
            for (int ni = 0; ni < 4; ni++)
                #pragma unroll
                for (int c = 0; c < 2; c++) {
                    int col = col0 + warp_n * 32 + ni * 8 + (lane & 3) * 2 + c;
                    float d = cn[ni][c] - 2.0f * acc[mi][ni][rp * 2 + c];
                    if (d < best_d) { best_d = d; best_c = col; }
                }
            unsigned long long p =
                ((unsigned long long)float_to_ordered(best_d) << 32) | (unsigned)best_c;
            float qd = best_d;
            #pragma unroll
            for (int m = 1; m < 4; m <<= 1) {
                unsigned long long q = __shfl_xor_sync(0xffffffffu, p, m);
                if (q < p) p = q;
                qd = fminf(qd, __shfl_xor_sync(0xffffffffu, qd, m));
            }
            if ((lane & 3) == 0) atomicMin(&g_best[row], p);
            // live global min (stale/torn read only raises thr -> still sound)
            unsigned long long gb = *((volatile unsigned long long*)&g_best[row]);
            float gl = ordered_to_float((unsigned)(gb >> 32));
            const float thr = fminf(qd, gl) + __ldg(&g_margin[row]);
            #pragma unroll
            for (int ni = 0; ni < 4; ni++)
                #pragma unroll
                for (int c = 0; c < 2; c++) {
                    int col = col0 + warp_n * 32 + ni * 8 + (lane & 3) * 2 + c;
                    float d = cn[ni][c] - 2.0f * acc[mi][ni][rp * 2 + c];
                    if (d <= thr) {
                        unsigned slot = atomicAdd(&g_candcnt[row], 1u);
                        if (slot < CAP)
                            g_cand[(size_t)row * CAP + slot] = (unsigned)col;
                    }
                }
        }
    }
}

// ================== pass 2: exact refinement (fp64) ========================
__device__ __forceinline__ double warp_exact_dist(const float* __restrict__ X,
                                                  const float* __restrict__ C,
                                                  int row, int col, int lane) {
    const float* xr = X + (size_t)row * DIM;
    const float* cr = C + (size_t)col * DIM;
    double dot = 0.0, cn = 0.0;
    for (int j = lane; j < DIM; j += 32) {
        double cv = (double)cr[j];
        dot += (double)xr[j] * cv;
        cn  += cv * cv;
    }
    #pragma unroll
    for (int o = 16; o > 0; o >>= 1) {
        dot += __shfl_down_sync(0xffffffffu, dot, o);
        cn  += __shfl_down_sync(0xffffffffu, cn,  o);
    }
    return cn - 2.0 * dot;   // valid on lane 0
}

__global__ void refine_kernel(const float* __restrict__ X, const float* __restrict__ C) {
    const int warp = (blockIdx.x * blockDim.x + threadIdx.x) >> 5;
    const int lane = threadIdx.x & 31;
    if (warp >= N_ROWS) return;
    const int row = warp;

    const unsigned cnt_raw = g_candcnt[row];
    double best_d = DBL_MAX;
    int    best_c = 0x7FFFFFFF;

    if (cnt_raw > CAP) {
        for (int col = 0; col < K_CODES; col++) {
            double d = warp_exact_dist(X, C, row, col, lane);
            if (lane == 0 && d < best_d) { best_d = d; best_c = col; }
        }
    } else {
        const int cnt = (int)cnt_raw;
        for (int i = 0; i < cnt; i++) {
            int c = (int)g_cand[(size_t)row * CAP + i];
            double d = warp_exact_dist(X, C, row, c, lane);
            if (lane == 0 && (d < best_d || (d == best_d && c < best_c))) {
                best_d = d; best_c = c;
            }
        }
    }
    if (lane == 0) g_idx[row] = (unsigned)best_c;
}

// ============================ gather =======================================
__global__ void gather_kernel(const float* __restrict__ C, const float* __restrict__ X,
                              float* __restrict__ out) {
    int n = blockIdx.x;
    unsigned idx = g_idx[n];
    const float4* src = (const float4*)(C + (size_t)idx * DIM);
    const float4* xs  = (const float4*)(X + (size_t)n * DIM);
    float4* d0 = (float4*)(out + (size_t)n * DIM);
    float4* d1 = (float4*)(out + ((size_t)N_ROWS + n) * DIM);
    int i = threadIdx.x;
    float4 q = src[i];
    float4 x = xs[i];
    d0[i] = q;
    float4 st;
    st.x = x.x + (q.x - x.x);
    st.y = x.y + (q.y - x.y);
    st.z = x.z + (q.z - x.z);
    st.w = x.w + (q.w - x.w);
    d1[i] = st;
}

// ===========================================================================
extern "C" void kernel_launch(void* const* d_in, const int* in_sizes, int n_in,
                              void* d_out, int out_size) {
    const float* x  = (const float*)d_in[0];
    const float* cb = (const float*)d_in[1];
    float* out = (float*)d_out;
    (void)in_sizes; (void)n_in; (void)out_size;

    cudaFuncSetAttribute(gemm_argmin_mma,
                         cudaFuncAttributeMaxDynamicSharedMemorySize, SMEM_TOTAL);

    split_x_kernel<<<(N_ROWS * DIM / 4 + 255) / 256, 256>>>(x, N_ROWS * DIM / 4);
    split_c_kernel<<<(K_CODES * DIM / 4 + 255) / 256, 256>>>(cb, K_CODES * DIM / 4);
    prep_x_kernel<<<(N_ROWS * 32 + 255) / 256, 256>>>(x);
    prep_c_kernel<<<(K_CODES * 32 + 255) / 256, 256>>>(cb);

    dim3 grid(K_CODES / BN, N_ROWS / BM);   // (64, 256)
    gemm_argmin_mma<<<grid, 256, SMEM_TOTAL>>>();

    refine_kernel<<<(N_ROWS * 32 + 255) / 256, 256>>>(x, cb);
    gather_kernel<<<N_ROWS, 128>>>(cb, x, out);
}